// round 1
// baseline (speedup 1.0000x reference)
#include <cuda_runtime.h>

// HyperGCN fused pipeline for V=500000, D=128, NE=1000000, K=8, H1=8, C=16.
// Sizes derived from in_sizes at launch; scratch statically sized for this problem.

#define VN    500000
#define NEDGE 1000000

// ---------------- scratch (device globals; no allocation allowed) ------------
__device__ float  g_proj[VN];          // random projection X @ rv
__device__ float  g_dinv[VN];          // degree, then rsqrt(degree)
__device__ float4 g_A[VN * 4];         // M buffer: 8 floats/row (L1,L2) or 16 (out3)
__device__ float4 g_B[VN * 2];         // spmm accumulator for layers 1,2 (8 floats/row)
__device__ float4 g_C[VN * 4];         // M3 buffer (16 floats/row)
__device__ int    g_Se[NEDGE];
__device__ int    g_Ie[NEDGE];
__device__ int    g_is64;              // 1 if E is int64, 0 if int32

// Vector reduction (no-return atomic add), sm_90+.
__device__ __forceinline__ void red_add_v4(float4* addr, float a, float b, float c, float d) {
    asm volatile("red.global.add.v4.f32 [%0], {%1, %2, %3, %4};"
                 :: "l"(addr), "f"(a), "f"(b), "f"(c), "f"(d)
                 : "memory");
}

// ---------------- K0: detect E dtype (int64 vs silently-int32) ---------------
__global__ void k0_detect(const long long* __restrict__ E, int V) {
    __shared__ int ok;
    if (threadIdx.x == 0) ok = 1;
    __syncthreads();
    // If the buffer is int32, reading it as int64 combines two random 32-bit
    // values -> out of [0, V) almost surely. 2048 checked slots is decisive.
    for (int i = threadIdx.x; i < 2048; i += blockDim.x) {
        long long v = E[i];
        if (v < 0 || v >= (long long)V) ok = 0;
    }
    __syncthreads();
    if (threadIdx.x == 0) g_is64 = ok;
}

// ---------------- K1: fused proj = X@rv and M1 = X@W1, deg init --------------
// 8 lanes per row, 4 rows per warp, 256 threads/block -> 32 rows/block.
__global__ void k1_proj_xw1(const float* __restrict__ X,
                            const float* __restrict__ rv,
                            const float* __restrict__ W1, int V) {
    __shared__ float s_rv[128];
    __shared__ float s_W1[1024];
    int t = threadIdx.x;
    if (t < 128) s_rv[t] = rv[t];
    for (int i = t; i < 1024; i += blockDim.x) s_W1[i] = W1[i];
    __syncthreads();

    int lane = t & 31;
    int l8   = lane & 7;
    int grp  = lane >> 3;
    int warp = t >> 5;
    int row  = blockIdx.x * 32 + warp * 4 + grp;
    bool valid = row < V;
    int r = valid ? row : 0;

    const float4* Xr = (const float4*)X + (size_t)r * 32;
    float accP = 0.f;
    float accW[8];
#pragma unroll
    for (int h = 0; h < 8; h++) accW[h] = 0.f;

#pragma unroll
    for (int j = 0; j < 4; j++) {
        float4 x = Xr[l8 + j * 8];              // 8 lanes cover 128B contiguous
        int d0 = l8 * 4 + j * 32;
        float xs[4] = {x.x, x.y, x.z, x.w};
#pragma unroll
        for (int q = 0; q < 4; q++) {
            int d = d0 + q;
            accP = fmaf(xs[q], s_rv[d], accP);
#pragma unroll
            for (int h = 0; h < 8; h++)
                accW[h] = fmaf(xs[q], s_W1[d * 8 + h], accW[h]);
        }
    }
    // reduce within each aligned 8-lane group
#pragma unroll
    for (int off = 4; off; off >>= 1) {
        accP += __shfl_xor_sync(0xffffffffu, accP, off);
#pragma unroll
        for (int h = 0; h < 8; h++)
            accW[h] += __shfl_xor_sync(0xffffffffu, accW[h], off);
    }
    if (valid && l8 == 0) {
        g_proj[row] = accP;
        g_A[(size_t)row * 2 + 0] = make_float4(accW[0], accW[1], accW[2], accW[3]);
        g_A[(size_t)row * 2 + 1] = make_float4(accW[4], accW[5], accW[6], accW[7]);
        g_dinv[row] = 1.0f;                     // degree init (+identity)
    }
}

// ---------------- K2: per-edge argmax/argmin + degree accumulation -----------
__global__ void k2_edges(const long long* __restrict__ E, int ne, int V) {
    int e = blockIdx.x * blockDim.x + threadIdx.x;
    if (e >= ne) return;
    int idx[8];
    if (g_is64) {
        const long long* Er = E + (size_t)e * 8;
#pragma unroll
        for (int j = 0; j < 8; j++) idx[j] = (int)Er[j];
    } else {
        const int* Ei = (const int*)E + (size_t)e * 8;
#pragma unroll
        for (int j = 0; j < 8; j++) idx[j] = Ei[j];
    }
    float pm = g_proj[idx[0]], pn = pm;
    int sm = idx[0], im = idx[0];
#pragma unroll
    for (int j = 1; j < 8; j++) {
        float p = g_proj[idx[j]];
        if (p > pm) { pm = p; sm = idx[j]; }    // strict: first-occurrence argmax
        if (p < pn) { pn = p; im = idx[j]; }    // strict: first-occurrence argmin
    }
    g_Se[e] = sm;
    g_Ie[e] = im;
    atomicAdd(&g_dinv[sm], 0.125f);
    atomicAdd(&g_dinv[im], 0.125f);
}

// ---------------- K3: dinv = rsqrt(deg); out1 = dinv^2 * M1 ------------------
__global__ void k3_dinv_init(int V) {
    int v = blockIdx.x * blockDim.x + threadIdx.x;
    if (v >= V) return;
    float dinv = rsqrtf(g_dinv[v]);
    g_dinv[v] = dinv;
    float c = dinv * dinv;
    float4 a0 = g_A[(size_t)v * 2], a1 = g_A[(size_t)v * 2 + 1];
    g_B[(size_t)v * 2]     = make_float4(c * a0.x, c * a0.y, c * a0.z, c * a0.w);
    g_B[(size_t)v * 2 + 1] = make_float4(c * a1.x, c * a1.y, c * a1.z, c * a1.w);
}

// ---------------- scatter F=8: B += coef * A[other endpoint] -----------------
__global__ void k_scatter8(int ne) {
    int e = blockIdx.x * blockDim.x + threadIdx.x;
    if (e >= ne) return;
    int s = g_Se[e], i = g_Ie[e];
    float c = 0.125f * g_dinv[s] * g_dinv[i];
    float4 s0 = g_A[(size_t)s * 2], s1 = g_A[(size_t)s * 2 + 1];
    float4 i0 = g_A[(size_t)i * 2], i1 = g_A[(size_t)i * 2 + 1];
    red_add_v4(&g_B[(size_t)s * 2],     c * i0.x, c * i0.y, c * i0.z, c * i0.w);
    red_add_v4(&g_B[(size_t)s * 2 + 1], c * i1.x, c * i1.y, c * i1.z, c * i1.w);
    red_add_v4(&g_B[(size_t)i * 2],     c * s0.x, c * s0.y, c * s0.z, c * s0.w);
    red_add_v4(&g_B[(size_t)i * 2 + 1], c * s1.x, c * s1.y, c * s1.z, c * s1.w);
}

// ------------- K5: h1 = relu(out1+b1); M2 = h1@W2; out2init = dinv^2*M2 ------
__global__ void k5_layer2(const float* __restrict__ W2, const float* __restrict__ b1, int V) {
    __shared__ float sW[64];
    __shared__ float sb[8];
    int t = threadIdx.x;
    if (t < 64) sW[t] = W2[t];
    if (t < 8)  sb[t] = b1[t];
    __syncthreads();
    int v = blockIdx.x * blockDim.x + t;
    if (v >= V) return;
    float4 o0 = g_B[(size_t)v * 2], o1 = g_B[(size_t)v * 2 + 1];
    float h[8] = {
        fmaxf(o0.x + sb[0], 0.f), fmaxf(o0.y + sb[1], 0.f),
        fmaxf(o0.z + sb[2], 0.f), fmaxf(o0.w + sb[3], 0.f),
        fmaxf(o1.x + sb[4], 0.f), fmaxf(o1.y + sb[5], 0.f),
        fmaxf(o1.z + sb[6], 0.f), fmaxf(o1.w + sb[7], 0.f)};
    float m[8];
#pragma unroll
    for (int j = 0; j < 8; j++) m[j] = 0.f;
#pragma unroll
    for (int d = 0; d < 8; d++)
#pragma unroll
        for (int j = 0; j < 8; j++)
            m[j] = fmaf(h[d], sW[d * 8 + j], m[j]);
    float dinv = g_dinv[v];
    float c = dinv * dinv;
    g_A[(size_t)v * 2]     = make_float4(m[0], m[1], m[2], m[3]);
    g_A[(size_t)v * 2 + 1] = make_float4(m[4], m[5], m[6], m[7]);
    g_B[(size_t)v * 2]     = make_float4(c * m[0], c * m[1], c * m[2], c * m[3]);
    g_B[(size_t)v * 2 + 1] = make_float4(c * m[4], c * m[5], c * m[6], c * m[7]);
}

// ------------- K7: h2 = relu(out2+b2); M3 = h2@W3 (16); out3init -------------
__global__ void k7_layer3(const float* __restrict__ W3, const float* __restrict__ b2, int V) {
    __shared__ float sW[128];   // [8,16]
    __shared__ float sb[8];
    int t = threadIdx.x;
    if (t < 128) sW[t] = W3[t];
    if (t < 8)   sb[t] = b2[t];
    __syncthreads();
    int v = blockIdx.x * blockDim.x + t;
    if (v >= V) return;
    float4 o0 = g_B[(size_t)v * 2], o1 = g_B[(size_t)v * 2 + 1];
    float h[8] = {
        fmaxf(o0.x + sb[0], 0.f), fmaxf(o0.y + sb[1], 0.f),
        fmaxf(o0.z + sb[2], 0.f), fmaxf(o0.w + sb[3], 0.f),
        fmaxf(o1.x + sb[4], 0.f), fmaxf(o1.y + sb[5], 0.f),
        fmaxf(o1.z + sb[6], 0.f), fmaxf(o1.w + sb[7], 0.f)};
    float m[16];
#pragma unroll
    for (int j = 0; j < 16; j++) m[j] = 0.f;
#pragma unroll
    for (int d = 0; d < 8; d++)
#pragma unroll
        for (int j = 0; j < 16; j++)
            m[j] = fmaf(h[d], sW[d * 16 + j], m[j]);
    float dinv = g_dinv[v];
    float c = dinv * dinv;
#pragma unroll
    for (int q = 0; q < 4; q++) {
        g_C[(size_t)v * 4 + q] = make_float4(m[4*q], m[4*q+1], m[4*q+2], m[4*q+3]);
        g_A[(size_t)v * 4 + q] = make_float4(c*m[4*q], c*m[4*q+1], c*m[4*q+2], c*m[4*q+3]);
    }
}

// ---------------- scatter F=16: A += coef * C[other endpoint] ----------------
__global__ void k_scatter16(int ne) {
    int e = blockIdx.x * blockDim.x + threadIdx.x;
    if (e >= ne) return;
    int s = g_Se[e], i = g_Ie[e];
    float c = 0.125f * g_dinv[s] * g_dinv[i];
    float4 sv[4], iv[4];
#pragma unroll
    for (int q = 0; q < 4; q++) { sv[q] = g_C[(size_t)s * 4 + q]; iv[q] = g_C[(size_t)i * 4 + q]; }
#pragma unroll
    for (int q = 0; q < 4; q++)
        red_add_v4(&g_A[(size_t)s * 4 + q], c * iv[q].x, c * iv[q].y, c * iv[q].z, c * iv[q].w);
#pragma unroll
    for (int q = 0; q < 4; q++)
        red_add_v4(&g_A[(size_t)i * 4 + q], c * sv[q].x, c * sv[q].y, c * sv[q].z, c * sv[q].w);
}

// ---------------- K9: h3 = relu(out3+b3); logit = h3.fc_w+fc_b; sigmoid ------
__global__ void k9_final(const float* __restrict__ b3, const float* __restrict__ fcw,
                         const float* __restrict__ fcb, float* __restrict__ out, int V) {
    __shared__ float sb[16];
    __shared__ float sw[16];
    __shared__ float sfb;
    int t = threadIdx.x;
    if (t < 16) { sb[t] = b3[t]; sw[t] = fcw[t]; }
    if (t == 0) sfb = fcb[0];
    __syncthreads();
    int v = blockIdx.x * blockDim.x + t;
    if (v >= V) return;
    float acc = sfb;
#pragma unroll
    for (int q = 0; q < 4; q++) {
        float4 a = g_A[(size_t)v * 4 + q];
        acc = fmaf(fmaxf(a.x + sb[4*q+0], 0.f), sw[4*q+0], acc);
        acc = fmaf(fmaxf(a.y + sb[4*q+1], 0.f), sw[4*q+1], acc);
        acc = fmaf(fmaxf(a.z + sb[4*q+2], 0.f), sw[4*q+2], acc);
        acc = fmaf(fmaxf(a.w + sb[4*q+3], 0.f), sw[4*q+3], acc);
    }
    out[v] = 1.0f / (1.0f + expf(-acc));
}

// ---------------- launch ------------------------------------------------------
extern "C" void kernel_launch(void* const* d_in, const int* in_sizes, int n_in,
                              void* d_out, int out_size) {
    const float*     X   = (const float*)d_in[0];
    const long long* E   = (const long long*)d_in[1];
    const float*     rv  = (const float*)d_in[2];
    const float*     W1  = (const float*)d_in[3];
    const float*     b1  = (const float*)d_in[4];
    const float*     W2  = (const float*)d_in[5];
    const float*     b2  = (const float*)d_in[6];
    const float*     W3  = (const float*)d_in[7];
    const float*     b3  = (const float*)d_in[8];
    const float*     fcw = (const float*)d_in[9];
    const float*     fcb = (const float*)d_in[10];
    float*           out = (float*)d_out;

    int V  = in_sizes[0] / 128;
    int ne = in_sizes[1] / 8;

    dim3 blk(256);
    int gb_node = (V + 255) / 256;
    int gb_edge = (ne + 255) / 256;
    int gb_k1   = (V + 31) / 32;

    k0_detect<<<1, 256>>>(E, V);
    k1_proj_xw1<<<gb_k1, blk>>>(X, rv, W1, V);
    k2_edges<<<gb_edge, blk>>>(E, ne, V);
    k3_dinv_init<<<gb_node, blk>>>(V);
    k_scatter8<<<gb_edge, blk>>>(ne);
    k5_layer2<<<gb_node, blk>>>(W2, b1, V);
    k_scatter8<<<gb_edge, blk>>>(ne);
    k7_layer3<<<gb_node, blk>>>(W3, b2, V);
    k_scatter16<<<gb_edge, blk>>>(ne);
    k9_final<<<gb_node, blk>>>(b3, fcw, fcb, out, V);
}

// round 3
// speedup vs baseline: 1.0414x; 1.0414x over previous
#include <cuda_runtime.h>

// HyperGCN: CSR-gather formulation. V=500000, D=128, NE=1000000, K=8, H1=8, C=16.

#define VN    500000
#define NEDGE 1000000

// ---------------- scratch (device globals; no allocation allowed) ------------
__device__ float  g_proj[VN];          // X @ rv
__device__ float  g_deg[VN];           // degree, then overwritten with rsqrt(degree)
__device__ int    g_cnt[VN];           // directed in-degree per node
__device__ int    g_row[VN];           // CSR row start
__device__ int    g_head[VN];          // fill cursors
__device__ int    g_Se[NEDGE];
__device__ int    g_Ie[NEDGE];
__device__ int    g_csr[2 * NEDGE];    // source node per directed edge
__device__ int    g_bsum[1024];
__device__ int    g_boff[1024];
__device__ float4 g_M1[VN * 2];        // X@W1 (8 f/row)
__device__ float4 g_M2[VN * 2];        // h1@W2 (8 f/row)
__device__ float4 g_M3[VN * 4];        // h2@W3 (16 f/row)
__device__ int    g_is64;

// ---------------- K0: detect E dtype (int64 vs silently-int32) ---------------
__global__ void k0_detect(const long long* __restrict__ E, int V) {
    __shared__ int ok;
    if (threadIdx.x == 0) ok = 1;
    __syncthreads();
    // int32 data read as int64 combines two random 32-bit words -> out of [0,V)
    // almost surely. 2048 slots checked is decisive.
    for (int i = threadIdx.x; i < 2048; i += blockDim.x) {
        long long v = E[i];
        if (v < 0 || v >= (long long)V) ok = 0;
    }
    __syncthreads();
    if (threadIdx.x == 0) g_is64 = ok;
}

// ---------------- K1: fused proj = X@rv and M1 = X@W1, deg init --------------
// 8 lanes per row, 4 rows per warp, 256 threads/block -> 32 rows/block.
__global__ void __launch_bounds__(256) k1_proj_xw1(
        const float* __restrict__ X,
        const float* __restrict__ rv,
        const float* __restrict__ W1, int V) {
    __shared__ float s_rv[128];
    __shared__ float s_W1[1024];
    int t = threadIdx.x;
    if (t < 128) s_rv[t] = rv[t];
    for (int i = t; i < 1024; i += blockDim.x) s_W1[i] = W1[i];
    __syncthreads();

    int lane = t & 31;
    int l8   = lane & 7;
    int grp  = lane >> 3;
    int warp = t >> 5;
    int row  = blockIdx.x * 32 + warp * 4 + grp;
    bool valid = row < V;
    int r = valid ? row : 0;

    const float4* Xr = (const float4*)X + (size_t)r * 32;
    float accP = 0.f;
    float accW[8];
#pragma unroll
    for (int h = 0; h < 8; h++) accW[h] = 0.f;

#pragma unroll
    for (int j = 0; j < 4; j++) {
        float4 x = Xr[l8 + j * 8];              // 8 lanes cover 128B contiguous
        int d0 = l8 * 4 + j * 32;
        float xs[4] = {x.x, x.y, x.z, x.w};
#pragma unroll
        for (int q = 0; q < 4; q++) {
            int d = d0 + q;
            accP = fmaf(xs[q], s_rv[d], accP);
#pragma unroll
            for (int h = 0; h < 8; h++)
                accW[h] = fmaf(xs[q], s_W1[d * 8 + h], accW[h]);
        }
    }
#pragma unroll
    for (int off = 4; off; off >>= 1) {
        accP += __shfl_xor_sync(0xffffffffu, accP, off);
#pragma unroll
        for (int h = 0; h < 8; h++)
            accW[h] += __shfl_xor_sync(0xffffffffu, accW[h], off);
    }
    if (valid && l8 == 0) {
        g_proj[row] = accP;
        g_M1[(size_t)row * 2 + 0] = make_float4(accW[0], accW[1], accW[2], accW[3]);
        g_M1[(size_t)row * 2 + 1] = make_float4(accW[4], accW[5], accW[6], accW[7]);
        g_deg[row] = 1.0f;                      // identity contribution
    }
}

// ---------------- K2: per-edge argmax/argmin + degree accumulation -----------
__global__ void __launch_bounds__(256) k2_edges(const long long* __restrict__ E, int ne, int V) {
    int e = blockIdx.x * blockDim.x + threadIdx.x;
    if (e >= ne) return;
    int idx[8];
    if (g_is64) {
        const longlong2* Er = (const longlong2*)(E + (size_t)e * 8);
#pragma unroll
        for (int j = 0; j < 4; j++) {
            longlong2 v = Er[j];
            idx[2 * j] = (int)v.x; idx[2 * j + 1] = (int)v.y;
        }
    } else {
        const int4* Ei = (const int4*)((const int*)E + (size_t)e * 8);
        int4 a = Ei[0], b = Ei[1];
        idx[0] = a.x; idx[1] = a.y; idx[2] = a.z; idx[3] = a.w;
        idx[4] = b.x; idx[5] = b.y; idx[6] = b.z; idx[7] = b.w;
    }
    float pm = __ldg(&g_proj[idx[0]]), pn = pm;
    int sm = idx[0], im = idx[0];
#pragma unroll
    for (int j = 1; j < 8; j++) {
        float p = __ldg(&g_proj[idx[j]]);
        if (p > pm) { pm = p; sm = idx[j]; }    // strict: first-occurrence argmax
        if (p < pn) { pn = p; im = idx[j]; }    // strict: first-occurrence argmin
    }
    g_Se[e] = sm;
    g_Ie[e] = im;
    atomicAdd(&g_deg[sm], 0.125f);
    atomicAdd(&g_deg[im], 0.125f);
}

// ---------------- kA: dinv, counts, intra-block exclusive scan ---------------
__global__ void kA_scan1(int V) {
    __shared__ int s[1024];
    int t = threadIdx.x;
    int v = blockIdx.x * 1024 + t;
    int c = 0;
    if (v < V) {
        float deg = g_deg[v];
        g_deg[v] = rsqrtf(deg);                 // overwrite with dinv
        c = (int)lrintf((deg - 1.0f) * 8.0f);   // exact: 0.125-sums are exact fp32
        g_cnt[v] = c;
    }
    s[t] = c;
    __syncthreads();
    // Hillis–Steele inclusive scan
    for (int off = 1; off < 1024; off <<= 1) {
        int add = (t >= off) ? s[t - off] : 0;
        __syncthreads();
        s[t] += add;
        __syncthreads();
    }
    if (v < V) g_row[v] = s[t] - c;             // intra-block exclusive
    if (t == 1023) g_bsum[blockIdx.x] = s[1023];
}

// ---------------- kB: scan block sums (single block) -------------------------
__global__ void kB_scan2(int nb) {
    __shared__ int s[1024];
    int t = threadIdx.x;
    int orig = (t < nb) ? g_bsum[t] : 0;
    s[t] = orig;
    __syncthreads();
    for (int off = 1; off < 1024; off <<= 1) {
        int add = (t >= off) ? s[t - off] : 0;
        __syncthreads();
        s[t] += add;
        __syncthreads();
    }
    g_boff[t] = s[t] - orig;                    // exclusive block offsets
}

// ---------------- kC: finalize row starts, init cursors ----------------------
__global__ void kC_finish(int V) {
    int v = blockIdx.x * blockDim.x + threadIdx.x;
    if (v >= V) return;
    int r = g_row[v] + g_boff[v >> 10];
    g_row[v] = r;
    g_head[v] = r;
}

// ---------------- kF: CSR fill (2M cheap scalar atomics) ---------------------
__global__ void __launch_bounds__(256) kF_fill(int ne) {
    int e = blockIdx.x * blockDim.x + threadIdx.x;
    if (e >= ne) return;
    int s = g_Se[e], i = g_Ie[e];
    int p1 = atomicAdd(&g_head[s], 1);
    g_csr[p1] = i;
    int p2 = atomicAdd(&g_head[i], 1);
    g_csr[p2] = s;
}

// ------- g1: gather SpMM on M1 (F=8) + relu(+b1) + @W2 -> M2 -----------------
__global__ void __launch_bounds__(256) g1_layer(
        const float* __restrict__ b1, const float* __restrict__ W2, int V) {
    __shared__ float sW[64];
    __shared__ float sb[8];
    int t = threadIdx.x;
    if (t < 64) sW[t] = W2[t];
    if (t < 8)  sb[t] = b1[t];
    __syncthreads();
    int v = blockIdx.x * blockDim.x + t;
    if (v >= V) return;
    float dinv = g_deg[v];
    float c0 = dinv * dinv;
    float4 m0 = g_M1[(size_t)v * 2], m1 = g_M1[(size_t)v * 2 + 1];
    float acc[8] = {c0*m0.x, c0*m0.y, c0*m0.z, c0*m0.w,
                    c0*m1.x, c0*m1.y, c0*m1.z, c0*m1.w};
    int start = g_row[v], n = g_cnt[v];
    for (int j = 0; j < n; j++) {
        int u = __ldg(&g_csr[start + j]);
        float cu = dinv * 0.125f * __ldg(&g_deg[u]);
        float4 u0 = __ldg(&g_M1[(size_t)u * 2]);
        float4 u1 = __ldg(&g_M1[(size_t)u * 2 + 1]);
        acc[0] = fmaf(cu, u0.x, acc[0]); acc[1] = fmaf(cu, u0.y, acc[1]);
        acc[2] = fmaf(cu, u0.z, acc[2]); acc[3] = fmaf(cu, u0.w, acc[3]);
        acc[4] = fmaf(cu, u1.x, acc[4]); acc[5] = fmaf(cu, u1.y, acc[5]);
        acc[6] = fmaf(cu, u1.z, acc[6]); acc[7] = fmaf(cu, u1.w, acc[7]);
    }
    float h[8];
#pragma unroll
    for (int k = 0; k < 8; k++) h[k] = fmaxf(acc[k] + sb[k], 0.f);
    float m[8];
#pragma unroll
    for (int k = 0; k < 8; k++) m[k] = 0.f;
#pragma unroll
    for (int d = 0; d < 8; d++)
#pragma unroll
        for (int k = 0; k < 8; k++)
            m[k] = fmaf(h[d], sW[d * 8 + k], m[k]);
    g_M2[(size_t)v * 2]     = make_float4(m[0], m[1], m[2], m[3]);
    g_M2[(size_t)v * 2 + 1] = make_float4(m[4], m[5], m[6], m[7]);
}

// ------- g2: gather SpMM on M2 (F=8) + relu(+b2) + @W3 -> M3 (16) ------------
__global__ void __launch_bounds__(256) g2_layer(
        const float* __restrict__ b2, const float* __restrict__ W3, int V) {
    __shared__ float sW[128];   // [8,16]
    __shared__ float sb[8];
    int t = threadIdx.x;
    if (t < 128) sW[t] = W3[t];
    if (t < 8)   sb[t] = b2[t];
    __syncthreads();
    int v = blockIdx.x * blockDim.x + t;
    if (v >= V) return;
    float dinv = g_deg[v];
    float c0 = dinv * dinv;
    float4 m0 = g_M2[(size_t)v * 2], m1 = g_M2[(size_t)v * 2 + 1];
    float acc[8] = {c0*m0.x, c0*m0.y, c0*m0.z, c0*m0.w,
                    c0*m1.x, c0*m1.y, c0*m1.z, c0*m1.w};
    int start = g_row[v], n = g_cnt[v];
    for (int j = 0; j < n; j++) {
        int u = __ldg(&g_csr[start + j]);
        float cu = dinv * 0.125f * __ldg(&g_deg[u]);
        float4 u0 = __ldg(&g_M2[(size_t)u * 2]);
        float4 u1 = __ldg(&g_M2[(size_t)u * 2 + 1]);
        acc[0] = fmaf(cu, u0.x, acc[0]); acc[1] = fmaf(cu, u0.y, acc[1]);
        acc[2] = fmaf(cu, u0.z, acc[2]); acc[3] = fmaf(cu, u0.w, acc[3]);
        acc[4] = fmaf(cu, u1.x, acc[4]); acc[5] = fmaf(cu, u1.y, acc[5]);
        acc[6] = fmaf(cu, u1.z, acc[6]); acc[7] = fmaf(cu, u1.w, acc[7]);
    }
    float h[8];
#pragma unroll
    for (int k = 0; k < 8; k++) h[k] = fmaxf(acc[k] + sb[k], 0.f);
    float m[16];
#pragma unroll
    for (int k = 0; k < 16; k++) m[k] = 0.f;
#pragma unroll
    for (int d = 0; d < 8; d++)
#pragma unroll
        for (int k = 0; k < 16; k++)
            m[k] = fmaf(h[d], sW[d * 16 + k], m[k]);
#pragma unroll
    for (int q = 0; q < 4; q++)
        g_M3[(size_t)v * 4 + q] = make_float4(m[4*q], m[4*q+1], m[4*q+2], m[4*q+3]);
}

// ------- g3: gather SpMM on M3 (F=16) + relu(+b3) + fc + sigmoid -> out ------
__global__ void __launch_bounds__(256) g3_layer(
        const float* __restrict__ b3, const float* __restrict__ fcw,
        const float* __restrict__ fcb, float* __restrict__ out, int V) {
    __shared__ float sb[16];
    __shared__ float sw[16];
    __shared__ float sfb;
    int t = threadIdx.x;
    if (t < 16) { sb[t] = b3[t]; sw[t] = fcw[t]; }
    if (t == 0) sfb = fcb[0];
    __syncthreads();
    int v = blockIdx.x * blockDim.x + t;
    if (v >= V) return;
    float dinv = g_deg[v];
    float c0 = dinv * dinv;
    float acc[16];
#pragma unroll
    for (int q = 0; q < 4; q++) {
        float4 m = g_M3[(size_t)v * 4 + q];
        acc[4*q] = c0*m.x; acc[4*q+1] = c0*m.y; acc[4*q+2] = c0*m.z; acc[4*q+3] = c0*m.w;
    }
    int start = g_row[v], n = g_cnt[v];
    for (int j = 0; j < n; j++) {
        int u = __ldg(&g_csr[start + j]);
        float cu = dinv * 0.125f * __ldg(&g_deg[u]);
#pragma unroll
        for (int q = 0; q < 4; q++) {
            float4 um = __ldg(&g_M3[(size_t)u * 4 + q]);
            acc[4*q]   = fmaf(cu, um.x, acc[4*q]);
            acc[4*q+1] = fmaf(cu, um.y, acc[4*q+1]);
            acc[4*q+2] = fmaf(cu, um.z, acc[4*q+2]);
            acc[4*q+3] = fmaf(cu, um.w, acc[4*q+3]);
        }
    }
    float logit = sfb;
#pragma unroll
    for (int k = 0; k < 16; k++)
        logit = fmaf(fmaxf(acc[k] + sb[k], 0.f), sw[k], logit);
    out[v] = 1.0f / (1.0f + expf(-logit));
}

// ---------------- launch ------------------------------------------------------
extern "C" void kernel_launch(void* const* d_in, const int* in_sizes, int n_in,
                              void* d_out, int out_size) {
    const float*     X   = (const float*)d_in[0];
    const long long* E   = (const long long*)d_in[1];
    const float*     rv  = (const float*)d_in[2];
    const float*     W1  = (const float*)d_in[3];
    const float*     b1  = (const float*)d_in[4];
    const float*     W2  = (const float*)d_in[5];
    const float*     b2  = (const float*)d_in[6];
    const float*     W3  = (const float*)d_in[7];
    const float*     b3  = (const float*)d_in[8];
    const float*     fcw = (const float*)d_in[9];
    const float*     fcb = (const float*)d_in[10];
    float*           out = (float*)d_out;

    int V  = in_sizes[0] / 128;
    int ne = in_sizes[1] / 8;
    int nb = (V + 1023) / 1024;

    dim3 blk(256);
    int gb_node = (V + 255) / 256;
    int gb_edge = (ne + 255) / 256;
    int gb_k1   = (V + 31) / 32;

    k0_detect<<<1, 256>>>(E, V);
    k1_proj_xw1<<<gb_k1, blk>>>(X, rv, W1, V);
    k2_edges<<<gb_edge, blk>>>(E, ne, V);
    kA_scan1<<<nb, 1024>>>(V);
    kB_scan2<<<1, 1024>>>(nb);
    kC_finish<<<gb_node, blk>>>(V);
    kF_fill<<<gb_edge, blk>>>(ne);
    g1_layer<<<gb_node, blk>>>(b1, W2, V);
    g2_layer<<<gb_node, blk>>>(b2, W3, V);
    g3_layer<<<gb_node, blk>>>(b3, fcw, fcb, out, V);
}

// round 4
// speedup vs baseline: 2.2981x; 2.2069x over previous
#include <cuda_runtime.h>

// HyperGCN: CSR-gather formulation. V=500000, D=128, NE=1000000, K=8, H1=8, C=16.

#define VN    500000
#define NEDGE 1000000

// ---------------- scratch (device globals; no allocation allowed) ------------
__device__ float  g_proj[VN];          // X @ rv
__device__ float  g_deg[VN];           // degree, then overwritten with rsqrt(degree)
__device__ int    g_cnt[VN];           // directed in-degree per node
__device__ int    g_row[VN];           // CSR row start
__device__ int    g_head[VN];          // fill cursors
__device__ int    g_Se[NEDGE];
__device__ int    g_Ie[NEDGE];
__device__ int    g_csr[2 * NEDGE];    // source node per directed edge
__device__ int    g_bsum[1024];
__device__ int    g_boff[1024];
__device__ float4 g_M1[VN * 2];        // X@W1 (8 f/row)
__device__ float4 g_M2[VN * 2];        // h1@W2 (8 f/row)
__device__ float4 g_M3[VN * 4];        // h2@W3 (16 f/row)
__device__ int    g_is64;

// ---------------- K0: detect E dtype (int64 vs silently-int32) ---------------
__global__ void k0_detect(const long long* __restrict__ E, int V) {
    __shared__ int ok;
    if (threadIdx.x == 0) ok = 1;
    __syncthreads();
    for (int i = threadIdx.x; i < 2048; i += blockDim.x) {
        long long v = E[i];
        if (v < 0 || v >= (long long)V) ok = 0;
    }
    __syncthreads();
    if (threadIdx.x == 0) g_is64 = ok;
}

// ---------------- K1: fused proj = X@rv and M1 = X@W1, deg init --------------
// 8 lanes per row, 4 rows per warp, 256 threads/block -> 32 rows/block.
// W1 stored TRANSPOSED in smem ([h][d]) so the per-h float4 load is
// conflict-free: lane address stride is 16B, 8-lane group covers 128B.
__global__ void __launch_bounds__(256) k1_proj_xw1(
        const float* __restrict__ X,
        const float* __restrict__ rv,
        const float* __restrict__ W1, int V) {
    __shared__ float s_rv[128];
    __shared__ float s_W1t[8 * 128];   // [h][d]
    int t = threadIdx.x;
    if (t < 128) s_rv[t] = rv[t];
    for (int i = t; i < 1024; i += blockDim.x) {
        int d = i >> 3, h = i & 7;
        s_W1t[h * 128 + d] = W1[i];    // W1 is [d][h] row-major: W1[d*8+h]
    }
    __syncthreads();

    int lane = t & 31;
    int l8   = lane & 7;
    int grp  = lane >> 3;
    int warp = t >> 5;
    int row  = blockIdx.x * 32 + warp * 4 + grp;
    bool valid = row < V;
    int r = valid ? row : 0;

    const float4* Xr = (const float4*)X + (size_t)r * 32;
    float accP = 0.f;
    float accW[8];
#pragma unroll
    for (int h = 0; h < 8; h++) accW[h] = 0.f;

#pragma unroll
    for (int j = 0; j < 4; j++) {
        float4 x = Xr[l8 + j * 8];              // 8 lanes cover 128B contiguous
        int d0 = j * 32 + l8 * 4;               // this thread's 4 consecutive dims
        float4 rv4 = *(const float4*)&s_rv[d0]; // conflict-free (stride 16B)
        accP = fmaf(x.x, rv4.x, accP);
        accP = fmaf(x.y, rv4.y, accP);
        accP = fmaf(x.z, rv4.z, accP);
        accP = fmaf(x.w, rv4.w, accP);
#pragma unroll
        for (int h = 0; h < 8; h++) {
            float4 w = *(const float4*)&s_W1t[h * 128 + d0];  // conflict-free
            accW[h] = fmaf(x.x, w.x, accW[h]);
            accW[h] = fmaf(x.y, w.y, accW[h]);
            accW[h] = fmaf(x.z, w.z, accW[h]);
            accW[h] = fmaf(x.w, w.w, accW[h]);
        }
    }
#pragma unroll
    for (int off = 4; off; off >>= 1) {
        accP += __shfl_xor_sync(0xffffffffu, accP, off);
#pragma unroll
        for (int h = 0; h < 8; h++)
            accW[h] += __shfl_xor_sync(0xffffffffu, accW[h], off);
    }
    if (valid && l8 == 0) {
        g_proj[row] = accP;
        g_M1[(size_t)row * 2 + 0] = make_float4(accW[0], accW[1], accW[2], accW[3]);
        g_M1[(size_t)row * 2 + 1] = make_float4(accW[4], accW[5], accW[6], accW[7]);
        g_deg[row] = 1.0f;                      // identity contribution
    }
}

// ---------------- K2: per-edge argmax/argmin + degree accumulation -----------
__global__ void __launch_bounds__(256) k2_edges(const long long* __restrict__ E, int ne, int V) {
    int e = blockIdx.x * blockDim.x + threadIdx.x;
    if (e >= ne) return;
    int idx[8];
    if (g_is64) {
        const longlong2* Er = (const longlong2*)(E + (size_t)e * 8);
#pragma unroll
        for (int j = 0; j < 4; j++) {
            longlong2 v = Er[j];
            idx[2 * j] = (int)v.x; idx[2 * j + 1] = (int)v.y;
        }
    } else {
        const int4* Ei = (const int4*)((const int*)E + (size_t)e * 8);
        int4 a = Ei[0], b = Ei[1];
        idx[0] = a.x; idx[1] = a.y; idx[2] = a.z; idx[3] = a.w;
        idx[4] = b.x; idx[5] = b.y; idx[6] = b.z; idx[7] = b.w;
    }
    float pm = __ldg(&g_proj[idx[0]]), pn = pm;
    int sm = idx[0], im = idx[0];
#pragma unroll
    for (int j = 1; j < 8; j++) {
        float p = __ldg(&g_proj[idx[j]]);
        if (p > pm) { pm = p; sm = idx[j]; }    // strict: first-occurrence argmax
        if (p < pn) { pn = p; im = idx[j]; }    // strict: first-occurrence argmin
    }
    g_Se[e] = sm;
    g_Ie[e] = im;
    atomicAdd(&g_deg[sm], 0.125f);
    atomicAdd(&g_deg[im], 0.125f);
}

// ---------------- kA: dinv, counts, intra-block exclusive scan ---------------
__global__ void kA_scan1(int V) {
    __shared__ int s[1024];
    int t = threadIdx.x;
    int v = blockIdx.x * 1024 + t;
    int c = 0;
    if (v < V) {
        float deg = g_deg[v];
        g_deg[v] = rsqrtf(deg);                 // overwrite with dinv
        c = (int)lrintf((deg - 1.0f) * 8.0f);   // exact: 0.125-sums are exact fp32
        g_cnt[v] = c;
    }
    s[t] = c;
    __syncthreads();
    for (int off = 1; off < 1024; off <<= 1) {
        int add = (t >= off) ? s[t - off] : 0;
        __syncthreads();
        s[t] += add;
        __syncthreads();
    }
    if (v < V) g_row[v] = s[t] - c;             // intra-block exclusive
    if (t == 1023) g_bsum[blockIdx.x] = s[1023];
}

// ---------------- kB: scan block sums (single block) -------------------------
__global__ void kB_scan2(int nb) {
    __shared__ int s[1024];
    int t = threadIdx.x;
    int orig = (t < nb) ? g_bsum[t] : 0;
    s[t] = orig;
    __syncthreads();
    for (int off = 1; off < 1024; off <<= 1) {
        int add = (t >= off) ? s[t - off] : 0;
        __syncthreads();
        s[t] += add;
        __syncthreads();
    }
    g_boff[t] = s[t] - orig;                    // exclusive block offsets
}

// ---------------- kC: finalize row starts, init cursors ----------------------
__global__ void kC_finish(int V) {
    int v = blockIdx.x * blockDim.x + threadIdx.x;
    if (v >= V) return;
    int r = g_row[v] + g_boff[v >> 10];
    g_row[v] = r;
    g_head[v] = r;
}

// ---------------- kF: CSR fill (2M cheap scalar atomics) ---------------------
__global__ void __launch_bounds__(256) kF_fill(int ne) {
    int e = blockIdx.x * blockDim.x + threadIdx.x;
    if (e >= ne) return;
    int s = g_Se[e], i = g_Ie[e];
    int p1 = atomicAdd(&g_head[s], 1);
    g_csr[p1] = i;
    int p2 = atomicAdd(&g_head[i], 1);
    g_csr[p2] = s;
}

// ------- g1: gather SpMM on M1 (F=8) + relu(+b1) + @W2 -> M2 -----------------
__global__ void __launch_bounds__(256) g1_layer(
        const float* __restrict__ b1, const float* __restrict__ W2, int V) {
    __shared__ float sW[64];
    __shared__ float sb[8];
    int t = threadIdx.x;
    if (t < 64) sW[t] = W2[t];
    if (t < 8)  sb[t] = b1[t];
    __syncthreads();
    int v = blockIdx.x * blockDim.x + t;
    if (v >= V) return;
    float dinv = g_deg[v];
    float c0 = dinv * dinv;
    float4 m0 = g_M1[(size_t)v * 2], m1 = g_M1[(size_t)v * 2 + 1];
    float acc[8] = {c0*m0.x, c0*m0.y, c0*m0.z, c0*m0.w,
                    c0*m1.x, c0*m1.y, c0*m1.z, c0*m1.w};
    int start = g_row[v], n = g_cnt[v];
    for (int j = 0; j < n; j++) {
        int u = __ldg(&g_csr[start + j]);
        float cu = dinv * 0.125f * __ldg(&g_deg[u]);
        float4 u0 = __ldg(&g_M1[(size_t)u * 2]);
        float4 u1 = __ldg(&g_M1[(size_t)u * 2 + 1]);
        acc[0] = fmaf(cu, u0.x, acc[0]); acc[1] = fmaf(cu, u0.y, acc[1]);
        acc[2] = fmaf(cu, u0.z, acc[2]); acc[3] = fmaf(cu, u0.w, acc[3]);
        acc[4] = fmaf(cu, u1.x, acc[4]); acc[5] = fmaf(cu, u1.y, acc[5]);
        acc[6] = fmaf(cu, u1.z, acc[6]); acc[7] = fmaf(cu, u1.w, acc[7]);
    }
    float h[8];
#pragma unroll
    for (int k = 0; k < 8; k++) h[k] = fmaxf(acc[k] + sb[k], 0.f);
    float m[8];
#pragma unroll
    for (int k = 0; k < 8; k++) m[k] = 0.f;
#pragma unroll
    for (int d = 0; d < 8; d++)
#pragma unroll
        for (int k = 0; k < 8; k++)
            m[k] = fmaf(h[d], sW[d * 8 + k], m[k]);
    g_M2[(size_t)v * 2]     = make_float4(m[0], m[1], m[2], m[3]);
    g_M2[(size_t)v * 2 + 1] = make_float4(m[4], m[5], m[6], m[7]);
}

// ------- g2: gather SpMM on M2 (F=8) + relu(+b2) + @W3 -> M3 (16) ------------
__global__ void __launch_bounds__(256) g2_layer(
        const float* __restrict__ b2, const float* __restrict__ W3, int V) {
    __shared__ float sW[128];   // [8,16]
    __shared__ float sb[8];
    int t = threadIdx.x;
    if (t < 128) sW[t] = W3[t];
    if (t < 8)   sb[t] = b2[t];
    __syncthreads();
    int v = blockIdx.x * blockDim.x + t;
    if (v >= V) return;
    float dinv = g_deg[v];
    float c0 = dinv * dinv;
    float4 m0 = g_M2[(size_t)v * 2], m1 = g_M2[(size_t)v * 2 + 1];
    float acc[8] = {c0*m0.x, c0*m0.y, c0*m0.z, c0*m0.w,
                    c0*m1.x, c0*m1.y, c0*m1.z, c0*m1.w};
    int start = g_row[v], n = g_cnt[v];
    for (int j = 0; j < n; j++) {
        int u = __ldg(&g_csr[start + j]);
        float cu = dinv * 0.125f * __ldg(&g_deg[u]);
        float4 u0 = __ldg(&g_M2[(size_t)u * 2]);
        float4 u1 = __ldg(&g_M2[(size_t)u * 2 + 1]);
        acc[0] = fmaf(cu, u0.x, acc[0]); acc[1] = fmaf(cu, u0.y, acc[1]);
        acc[2] = fmaf(cu, u0.z, acc[2]); acc[3] = fmaf(cu, u0.w, acc[3]);
        acc[4] = fmaf(cu, u1.x, acc[4]); acc[5] = fmaf(cu, u1.y, acc[5]);
        acc[6] = fmaf(cu, u1.z, acc[6]); acc[7] = fmaf(cu, u1.w, acc[7]);
    }
    float h[8];
#pragma unroll
    for (int k = 0; k < 8; k++) h[k] = fmaxf(acc[k] + sb[k], 0.f);
    float m[16];
#pragma unroll
    for (int k = 0; k < 16; k++) m[k] = 0.f;
#pragma unroll
    for (int d = 0; d < 8; d++)
#pragma unroll
        for (int k = 0; k < 16; k++)
            m[k] = fmaf(h[d], sW[d * 16 + k], m[k]);
#pragma unroll
    for (int q = 0; q < 4; q++)
        g_M3[(size_t)v * 4 + q] = make_float4(m[4*q], m[4*q+1], m[4*q+2], m[4*q+3]);
}

// ------- g3: gather SpMM on M3 (F=16) + relu(+b3) + fc + sigmoid -> out ------
__global__ void __launch_bounds__(256) g3_layer(
        const float* __restrict__ b3, const float* __restrict__ fcw,
        const float* __restrict__ fcb, float* __restrict__ out, int V) {
    __shared__ float sb[16];
    __shared__ float sw[16];
    __shared__ float sfb;
    int t = threadIdx.x;
    if (t < 16) { sb[t] = b3[t]; sw[t] = fcw[t]; }
    if (t == 0) sfb = fcb[0];
    __syncthreads();
    int v = blockIdx.x * blockDim.x + t;
    if (v >= V) return;
    float dinv = g_deg[v];
    float c0 = dinv * dinv;
    float acc[16];
#pragma unroll
    for (int q = 0; q < 4; q++) {
        float4 m = g_M3[(size_t)v * 4 + q];
        acc[4*q] = c0*m.x; acc[4*q+1] = c0*m.y; acc[4*q+2] = c0*m.z; acc[4*q+3] = c0*m.w;
    }
    int start = g_row[v], n = g_cnt[v];
    for (int j = 0; j < n; j++) {
        int u = __ldg(&g_csr[start + j]);
        float cu = dinv * 0.125f * __ldg(&g_deg[u]);
#pragma unroll
        for (int q = 0; q < 4; q++) {
            float4 um = __ldg(&g_M3[(size_t)u * 4 + q]);
            acc[4*q]   = fmaf(cu, um.x, acc[4*q]);
            acc[4*q+1] = fmaf(cu, um.y, acc[4*q+1]);
            acc[4*q+2] = fmaf(cu, um.z, acc[4*q+2]);
            acc[4*q+3] = fmaf(cu, um.w, acc[4*q+3]);
        }
    }
    float logit = sfb;
#pragma unroll
    for (int k = 0; k < 16; k++)
        logit = fmaf(fmaxf(acc[k] + sb[k], 0.f), sw[k], logit);
    out[v] = 1.0f / (1.0f + expf(-logit));
}

// ---------------- launch ------------------------------------------------------
extern "C" void kernel_launch(void* const* d_in, const int* in_sizes, int n_in,
                              void* d_out, int out_size) {
    const float*     X   = (const float*)d_in[0];
    const long long* E   = (const long long*)d_in[1];
    const float*     rv  = (const float*)d_in[2];
    const float*     W1  = (const float*)d_in[3];
    const float*     b1  = (const float*)d_in[4];
    const float*     W2  = (const float*)d_in[5];
    const float*     b2  = (const float*)d_in[6];
    const float*     W3  = (const float*)d_in[7];
    const float*     b3  = (const float*)d_in[8];
    const float*     fcw = (const float*)d_in[9];
    const float*     fcb = (const float*)d_in[10];
    float*           out = (float*)d_out;

    int V  = in_sizes[0] / 128;
    int ne = in_sizes[1] / 8;
    int nb = (V + 1023) / 1024;

    dim3 blk(256);
    int gb_node = (V + 255) / 256;
    int gb_edge = (ne + 255) / 256;
    int gb_k1   = (V + 31) / 32;

    k0_detect<<<1, 256>>>(E, V);
    k1_proj_xw1<<<gb_k1, blk>>>(X, rv, W1, V);
    k2_edges<<<gb_edge, blk>>>(E, ne, V);
    kA_scan1<<<nb, 1024>>>(V);
    kB_scan2<<<1, 1024>>>(nb);
    kC_finish<<<gb_node, blk>>>(V);
    kF_fill<<<gb_edge, blk>>>(ne);
    g1_layer<<<gb_node, blk>>>(b1, W2, V);
    g2_layer<<<gb_node, blk>>>(b2, W3, V);
    g3_layer<<<gb_node, blk>>>(b3, fcw, fcb, out, V);
}

// round 5
// speedup vs baseline: 2.3738x; 1.0329x over previous
#include <cuda_runtime.h>

// HyperGCN: CSR-gather, pre-scaled features. V=500000, D=128, NE=1e6, K=8, H1=8, C=16.

#define VN    500000
#define NEDGE 1000000

// ---------------- scratch (device globals; no allocation allowed) ------------
__device__ float  g_proj[VN];          // X @ rv
__device__ float  g_deg[VN];           // degree, then overwritten with rsqrt(degree)
__device__ int    g_row[VN + 1];       // CSR row starts (prefix, +1 sentinel)
__device__ int    g_head[VN];          // fill cursors
__device__ int    g_Se[NEDGE];
__device__ int    g_Ie[NEDGE];
__device__ int    g_csr[2 * NEDGE];    // source node per directed edge
__device__ int    g_bsum[1024];
__device__ float4 g_M1[VN * 2];        // dinv*(X@W1)      (8 f/row, scaled in kA)
__device__ float4 g_M2[VN * 2];        // dinv*(h1@W2)     (8 f/row)
__device__ float4 g_M3[VN * 4];        // dinv*(h2@W3)     (16 f/row)
__device__ int    g_is64;

// ---------------- K0: detect E dtype (int64 vs silently-int32) ---------------
__global__ void k0_detect(const long long* __restrict__ E, int V) {
    __shared__ int ok;
    if (threadIdx.x == 0) ok = 1;
    __syncthreads();
    for (int i = threadIdx.x; i < 2048; i += blockDim.x) {
        long long v = E[i];
        if (v < 0 || v >= (long long)V) ok = 0;
    }
    __syncthreads();
    if (threadIdx.x == 0) g_is64 = ok;
}

// ---------------- K1: fused proj = X@rv and M1 = X@W1, deg init --------------
// 8 lanes per row, 4 rows per warp; W1 transposed in smem -> conflict-free LDS.128.
__global__ void __launch_bounds__(256) k1_proj_xw1(
        const float* __restrict__ X,
        const float* __restrict__ rv,
        const float* __restrict__ W1, int V) {
    __shared__ float s_rv[128];
    __shared__ float s_W1t[8 * 128];   // [h][d]
    int t = threadIdx.x;
    if (t < 128) s_rv[t] = rv[t];
    for (int i = t; i < 1024; i += blockDim.x) {
        int d = i >> 3, h = i & 7;
        s_W1t[h * 128 + d] = W1[i];    // W1 is [d][h] row-major
    }
    __syncthreads();

    int lane = t & 31;
    int l8   = lane & 7;
    int grp  = lane >> 3;
    int warp = t >> 5;
    int row  = blockIdx.x * 32 + warp * 4 + grp;
    bool valid = row < V;
    int r = valid ? row : 0;

    const float4* Xr = (const float4*)X + (size_t)r * 32;
    float accP = 0.f;
    float accW[8];
#pragma unroll
    for (int h = 0; h < 8; h++) accW[h] = 0.f;

#pragma unroll
    for (int j = 0; j < 4; j++) {
        float4 x = Xr[l8 + j * 8];
        int d0 = j * 32 + l8 * 4;
        float4 rv4 = *(const float4*)&s_rv[d0];
        accP = fmaf(x.x, rv4.x, accP);
        accP = fmaf(x.y, rv4.y, accP);
        accP = fmaf(x.z, rv4.z, accP);
        accP = fmaf(x.w, rv4.w, accP);
#pragma unroll
        for (int h = 0; h < 8; h++) {
            float4 w = *(const float4*)&s_W1t[h * 128 + d0];
            accW[h] = fmaf(x.x, w.x, accW[h]);
            accW[h] = fmaf(x.y, w.y, accW[h]);
            accW[h] = fmaf(x.z, w.z, accW[h]);
            accW[h] = fmaf(x.w, w.w, accW[h]);
        }
    }
#pragma unroll
    for (int off = 4; off; off >>= 1) {
        accP += __shfl_xor_sync(0xffffffffu, accP, off);
#pragma unroll
        for (int h = 0; h < 8; h++)
            accW[h] += __shfl_xor_sync(0xffffffffu, accW[h], off);
    }
    if (valid && l8 == 0) {
        g_proj[row] = accP;
        g_M1[(size_t)row * 2 + 0] = make_float4(accW[0], accW[1], accW[2], accW[3]);
        g_M1[(size_t)row * 2 + 1] = make_float4(accW[4], accW[5], accW[6], accW[7]);
        g_deg[row] = 1.0f;                      // identity contribution
    }
}

// ---------------- K2: per-edge argmax/argmin + degree accumulation -----------
__global__ void __launch_bounds__(256) k2_edges(const long long* __restrict__ E, int ne, int V) {
    int e = blockIdx.x * blockDim.x + threadIdx.x;
    if (e >= ne) return;
    int idx[8];
    if (g_is64) {
        const longlong2* Er = (const longlong2*)(E + (size_t)e * 8);
#pragma unroll
        for (int j = 0; j < 4; j++) {
            longlong2 v = Er[j];
            idx[2 * j] = (int)v.x; idx[2 * j + 1] = (int)v.y;
        }
    } else {
        const int4* Ei = (const int4*)((const int*)E + (size_t)e * 8);
        int4 a = Ei[0], b = Ei[1];
        idx[0] = a.x; idx[1] = a.y; idx[2] = a.z; idx[3] = a.w;
        idx[4] = b.x; idx[5] = b.y; idx[6] = b.z; idx[7] = b.w;
    }
    float pm = __ldg(&g_proj[idx[0]]), pn = pm;
    int sm = idx[0], im = idx[0];
#pragma unroll
    for (int j = 1; j < 8; j++) {
        float p = __ldg(&g_proj[idx[j]]);
        if (p > pm) { pm = p; sm = idx[j]; }    // strict: first-occurrence argmax
        if (p < pn) { pn = p; im = idx[j]; }    // strict: first-occurrence argmin
    }
    g_Se[e] = sm;
    g_Ie[e] = im;
    atomicAdd(&g_deg[sm], 0.125f);
    atomicAdd(&g_deg[im], 0.125f);
}

// ----- kA: dinv; scale M1 in place by dinv; intra-block exclusive scan -------
__global__ void kA_scan1(int V) {
    __shared__ int s[1024];
    int t = threadIdx.x;
    int v = blockIdx.x * 1024 + t;
    int c = 0;
    if (v < V) {
        float deg = g_deg[v];
        float dinv = rsqrtf(deg);
        g_deg[v] = dinv;
        c = (int)lrintf((deg - 1.0f) * 8.0f);   // exact: 0.125-sums are exact fp32
        float4 m0 = g_M1[(size_t)v * 2], m1 = g_M1[(size_t)v * 2 + 1];
        g_M1[(size_t)v * 2]     = make_float4(dinv*m0.x, dinv*m0.y, dinv*m0.z, dinv*m0.w);
        g_M1[(size_t)v * 2 + 1] = make_float4(dinv*m1.x, dinv*m1.y, dinv*m1.z, dinv*m1.w);
    }
    s[t] = c;
    __syncthreads();
    for (int off = 1; off < 1024; off <<= 1) {
        int add = (t >= off) ? s[t - off] : 0;
        __syncthreads();
        s[t] += add;
        __syncthreads();
    }
    if (v < V) g_row[v] = s[t] - c;             // intra-block exclusive
    if (t == 1023) g_bsum[blockIdx.x] = s[1023];
}

// ----- kC: scan block sums locally; finalize row starts; init cursors --------
// 1024-thread blocks, one per 1024-node chunk (same blocking as kA).
__global__ void kC_finish(int V, int nb, int total) {
    __shared__ int s[1024];
    int t = threadIdx.x;
    s[t] = (t < nb) ? g_bsum[t] : 0;
    __syncthreads();
    for (int off = 1; off < 1024; off <<= 1) {
        int add = (t >= off) ? s[t - off] : 0;
        __syncthreads();
        s[t] += add;
        __syncthreads();
    }
    int b = blockIdx.x;
    int boff = (b == 0) ? 0 : s[b - 1];
    int v = b * 1024 + t;
    if (v < V) {
        int r = g_row[v] + boff;
        g_row[v] = r;
        g_head[v] = r;
    }
    if (b == 0 && t == 0) g_row[V] = total;
}

// ---------------- kF: CSR fill (2M cheap scalar atomics) ---------------------
__global__ void __launch_bounds__(256) kF_fill(int ne) {
    int e = blockIdx.x * blockDim.x + threadIdx.x;
    if (e >= ne) return;
    int s = g_Se[e], i = g_Ie[e];
    int p1 = atomicAdd(&g_head[s], 1);
    g_csr[p1] = i;
    int p2 = atomicAdd(&g_head[i], 1);
    g_csr[p2] = s;
}

// ------- g1: gather on scaled M1 + relu(+b1) + @W2 -> scaled M2 --------------
__global__ void __launch_bounds__(256) g1_layer(
        const float* __restrict__ b1, const float* __restrict__ W2, int V) {
    __shared__ float sW[64];
    __shared__ float sb[8];
    int t = threadIdx.x;
    if (t < 64) sW[t] = W2[t];
    if (t < 8)  sb[t] = b1[t];
    __syncthreads();
    int v = blockIdx.x * blockDim.x + t;
    if (v >= V) return;
    float dinv = g_deg[v];
    float4 m0 = g_M1[(size_t)v * 2], m1 = g_M1[(size_t)v * 2 + 1];
    float self[8] = {m0.x, m0.y, m0.z, m0.w, m1.x, m1.y, m1.z, m1.w};
    float acc[8] = {0.f, 0.f, 0.f, 0.f, 0.f, 0.f, 0.f, 0.f};
    int start = g_row[v], end = g_row[v + 1];
    for (int j = start; j < end; j++) {
        int u = __ldg(&g_csr[j]);
        float4 u0 = __ldg(&g_M1[(size_t)u * 2]);
        float4 u1 = __ldg(&g_M1[(size_t)u * 2 + 1]);
        acc[0] += u0.x; acc[1] += u0.y; acc[2] += u0.z; acc[3] += u0.w;
        acc[4] += u1.x; acc[5] += u1.y; acc[6] += u1.z; acc[7] += u1.w;
    }
    float h[8];
#pragma unroll
    for (int k = 0; k < 8; k++)
        h[k] = fmaxf(dinv * fmaf(0.125f, acc[k], self[k]) + sb[k], 0.f);
    float m[8];
#pragma unroll
    for (int k = 0; k < 8; k++) m[k] = 0.f;
#pragma unroll
    for (int d = 0; d < 8; d++)
#pragma unroll
        for (int k = 0; k < 8; k++)
            m[k] = fmaf(h[d], sW[d * 8 + k], m[k]);
    // write pre-scaled for next layer: M2s = dinv * M2
    g_M2[(size_t)v * 2]     = make_float4(dinv*m[0], dinv*m[1], dinv*m[2], dinv*m[3]);
    g_M2[(size_t)v * 2 + 1] = make_float4(dinv*m[4], dinv*m[5], dinv*m[6], dinv*m[7]);
}

// ------- g2: gather on scaled M2 + relu(+b2) + @W3 -> scaled M3 (16) ---------
__global__ void __launch_bounds__(256) g2_layer(
        const float* __restrict__ b2, const float* __restrict__ W3, int V) {
    __shared__ float sW[128];   // [8,16]
    __shared__ float sb[8];
    int t = threadIdx.x;
    if (t < 128) sW[t] = W3[t];
    if (t < 8)   sb[t] = b2[t];
    __syncthreads();
    int v = blockIdx.x * blockDim.x + t;
    if (v >= V) return;
    float dinv = g_deg[v];
    float4 m0 = g_M2[(size_t)v * 2], m1 = g_M2[(size_t)v * 2 + 1];
    float self[8] = {m0.x, m0.y, m0.z, m0.w, m1.x, m1.y, m1.z, m1.w};
    float acc[8] = {0.f, 0.f, 0.f, 0.f, 0.f, 0.f, 0.f, 0.f};
    int start = g_row[v], end = g_row[v + 1];
    for (int j = start; j < end; j++) {
        int u = __ldg(&g_csr[j]);
        float4 u0 = __ldg(&g_M2[(size_t)u * 2]);
        float4 u1 = __ldg(&g_M2[(size_t)u * 2 + 1]);
        acc[0] += u0.x; acc[1] += u0.y; acc[2] += u0.z; acc[3] += u0.w;
        acc[4] += u1.x; acc[5] += u1.y; acc[6] += u1.z; acc[7] += u1.w;
    }
    float h[8];
#pragma unroll
    for (int k = 0; k < 8; k++)
        h[k] = fmaxf(dinv * fmaf(0.125f, acc[k], self[k]) + sb[k], 0.f);
    float m[16];
#pragma unroll
    for (int k = 0; k < 16; k++) m[k] = 0.f;
#pragma unroll
    for (int d = 0; d < 8; d++)
#pragma unroll
        for (int k = 0; k < 16; k++)
            m[k] = fmaf(h[d], sW[d * 16 + k], m[k]);
#pragma unroll
    for (int q = 0; q < 4; q++)
        g_M3[(size_t)v * 4 + q] =
            make_float4(dinv*m[4*q], dinv*m[4*q+1], dinv*m[4*q+2], dinv*m[4*q+3]);
}

// ------- g3: gather on scaled M3 (16) + relu(+b3) + fc + sigmoid -> out ------
__global__ void __launch_bounds__(256) g3_layer(
        const float* __restrict__ b3, const float* __restrict__ fcw,
        const float* __restrict__ fcb, float* __restrict__ out, int V) {
    __shared__ float sb[16];
    __shared__ float sw[16];
    __shared__ float sfb;
    int t = threadIdx.x;
    if (t < 16) { sb[t] = b3[t]; sw[t] = fcw[t]; }
    if (t == 0) sfb = fcb[0];
    __syncthreads();
    int v = blockIdx.x * blockDim.x + t;
    if (v >= V) return;
    float dinv = g_deg[v];
    float self[16], acc[16];
#pragma unroll
    for (int q = 0; q < 4; q++) {
        float4 m = g_M3[(size_t)v * 4 + q];
        self[4*q] = m.x; self[4*q+1] = m.y; self[4*q+2] = m.z; self[4*q+3] = m.w;
        acc[4*q] = 0.f; acc[4*q+1] = 0.f; acc[4*q+2] = 0.f; acc[4*q+3] = 0.f;
    }
    int start = g_row[v], end = g_row[v + 1];
    for (int j = start; j < end; j++) {
        int u = __ldg(&g_csr[j]);
#pragma unroll
        for (int q = 0; q < 4; q++) {
            float4 um = __ldg(&g_M3[(size_t)u * 4 + q]);
            acc[4*q]   += um.x;
            acc[4*q+1] += um.y;
            acc[4*q+2] += um.z;
            acc[4*q+3] += um.w;
        }
    }
    float logit = sfb;
#pragma unroll
    for (int k = 0; k < 16; k++)
        logit = fmaf(fmaxf(dinv * fmaf(0.125f, acc[k], self[k]) + sb[k], 0.f),
                     sw[k], logit);
    out[v] = 1.0f / (1.0f + expf(-logit));
}

// ---------------- launch ------------------------------------------------------
extern "C" void kernel_launch(void* const* d_in, const int* in_sizes, int n_in,
                              void* d_out, int out_size) {
    const float*     X   = (const float*)d_in[0];
    const long long* E   = (const long long*)d_in[1];
    const float*     rv  = (const float*)d_in[2];
    const float*     W1  = (const float*)d_in[3];
    const float*     b1  = (const float*)d_in[4];
    const float*     W2  = (const float*)d_in[5];
    const float*     b2  = (const float*)d_in[6];
    const float*     W3  = (const float*)d_in[7];
    const float*     b3  = (const float*)d_in[8];
    const float*     fcw = (const float*)d_in[9];
    const float*     fcb = (const float*)d_in[10];
    float*           out = (float*)d_out;

    int V  = in_sizes[0] / 128;
    int ne = in_sizes[1] / 8;
    int nb = (V + 1023) / 1024;

    dim3 blk(256);
    int gb_node = (V + 255) / 256;
    int gb_edge = (ne + 255) / 256;
    int gb_k1   = (V + 31) / 32;

    k0_detect<<<1, 256>>>(E, V);
    k1_proj_xw1<<<gb_k1, blk>>>(X, rv, W1, V);
    k2_edges<<<gb_edge, blk>>>(E, ne, V);
    kA_scan1<<<nb, 1024>>>(V);
    kC_finish<<<nb, 1024>>>(V, nb, 2 * ne);
    kF_fill<<<gb_edge, blk>>>(ne);
    g1_layer<<<gb_node, blk>>>(b1, W2, V);
    g2_layer<<<gb_node, blk>>>(b2, W3, V);
    g3_layer<<<gb_node, blk>>>(b3, fcw, fcb, out, V);
}

// round 6
// speedup vs baseline: 2.5702x; 1.0827x over previous
#include <cuda_runtime.h>
#include <cuda_fp16.h>

// HyperGCN: CSR-gather, pre-scaled features, fp16 last-layer features.
// V=500000, D=128, NE=1e6, K=8, H1=8, C=16.

#define VN    500000
#define NEDGE 1000000

// ---------------- scratch (device globals; no allocation allowed) ------------
__device__ float  g_proj[VN];          // X @ rv
__device__ float  g_deg[VN];           // degree, then overwritten with rsqrt(degree)
__device__ int    g_row[VN + 1];       // CSR row starts (prefix, +1 sentinel)
__device__ int    g_head[VN];          // fill cursors
__device__ int2   g_SI[NEDGE];         // (Se, Ie) per edge
__device__ int    g_csr[2 * NEDGE];    // source node per directed edge
__device__ int    g_bsum[1024];
__device__ float4 g_M1[VN * 2];        // dinv*(X@W1)   (8 f/row, scaled in kA)
__device__ float4 g_M2[VN * 2];        // dinv*(h1@W2)  (8 f/row)
__device__ uint4  g_M3h[VN * 2];       // dinv*(h2@W3)  (16 halves/row = 32B)

// ---------------- K1: fused proj = X@rv and M1 = X@W1, deg init --------------
// 8 lanes per row, 4 rows per warp; W1 transposed in smem -> conflict-free LDS.128.
__global__ void __launch_bounds__(256) k1_proj_xw1(
        const float* __restrict__ X,
        const float* __restrict__ rv,
        const float* __restrict__ W1, int V) {
    __shared__ float s_rv[128];
    __shared__ float s_W1t[8 * 128];   // [h][d]
    int t = threadIdx.x;
    if (t < 128) s_rv[t] = rv[t];
    for (int i = t; i < 1024; i += blockDim.x) {
        int d = i >> 3, h = i & 7;
        s_W1t[h * 128 + d] = W1[i];    // W1 is [d][h] row-major
    }
    __syncthreads();

    int lane = t & 31;
    int l8   = lane & 7;
    int grp  = lane >> 3;
    int warp = t >> 5;
    int row  = blockIdx.x * 32 + warp * 4 + grp;
    bool valid = row < V;
    int r = valid ? row : 0;

    const float4* Xr = (const float4*)X + (size_t)r * 32;
    float accP = 0.f;
    float accW[8];
#pragma unroll
    for (int h = 0; h < 8; h++) accW[h] = 0.f;

#pragma unroll
    for (int j = 0; j < 4; j++) {
        float4 x = Xr[l8 + j * 8];
        int d0 = j * 32 + l8 * 4;
        float4 rv4 = *(const float4*)&s_rv[d0];
        accP = fmaf(x.x, rv4.x, accP);
        accP = fmaf(x.y, rv4.y, accP);
        accP = fmaf(x.z, rv4.z, accP);
        accP = fmaf(x.w, rv4.w, accP);
#pragma unroll
        for (int h = 0; h < 8; h++) {
            float4 w = *(const float4*)&s_W1t[h * 128 + d0];
            accW[h] = fmaf(x.x, w.x, accW[h]);
            accW[h] = fmaf(x.y, w.y, accW[h]);
            accW[h] = fmaf(x.z, w.z, accW[h]);
            accW[h] = fmaf(x.w, w.w, accW[h]);
        }
    }
#pragma unroll
    for (int off = 4; off; off >>= 1) {
        accP += __shfl_xor_sync(0xffffffffu, accP, off);
#pragma unroll
        for (int h = 0; h < 8; h++)
            accW[h] += __shfl_xor_sync(0xffffffffu, accW[h], off);
    }
    if (valid && l8 == 0) {
        g_proj[row] = accP;
        g_M1[(size_t)row * 2 + 0] = make_float4(accW[0], accW[1], accW[2], accW[3]);
        g_M1[(size_t)row * 2 + 1] = make_float4(accW[4], accW[5], accW[6], accW[7]);
        g_deg[row] = 1.0f;                      // identity contribution
    }
}

// ------- K2: inline dtype detect + per-edge argmax/argmin + degrees ----------
__global__ void __launch_bounds__(256) k2_edges(const long long* __restrict__ E, int ne, int V) {
    __shared__ int s_is64;
    if (threadIdx.x == 0) s_is64 = 1;
    __syncthreads();
    // int32 data read as int64 pairs two random words -> out of [0,V) w.p. ~1-2e-6
    // per slot; 64 slots checked per block is decisive and deterministic.
    if (threadIdx.x < 64) {
        long long v = E[threadIdx.x];
        if (v < 0 || v >= (long long)V) atomicAnd(&s_is64, 0);
    }
    __syncthreads();
    int is64 = s_is64;

    int e = blockIdx.x * blockDim.x + threadIdx.x;
    if (e >= ne) return;
    int idx[8];
    if (is64) {
        const longlong2* Er = (const longlong2*)(E + (size_t)e * 8);
#pragma unroll
        for (int j = 0; j < 4; j++) {
            longlong2 v = Er[j];
            idx[2 * j] = (int)v.x; idx[2 * j + 1] = (int)v.y;
        }
    } else {
        const int4* Ei = (const int4*)((const int*)E + (size_t)e * 8);
        int4 a = Ei[0], b = Ei[1];
        idx[0] = a.x; idx[1] = a.y; idx[2] = a.z; idx[3] = a.w;
        idx[4] = b.x; idx[5] = b.y; idx[6] = b.z; idx[7] = b.w;
    }
    float pm = __ldg(&g_proj[idx[0]]), pn = pm;
    int sm = idx[0], im = idx[0];
#pragma unroll
    for (int j = 1; j < 8; j++) {
        float p = __ldg(&g_proj[idx[j]]);
        if (p > pm) { pm = p; sm = idx[j]; }    // strict: first-occurrence argmax
        if (p < pn) { pn = p; im = idx[j]; }    // strict: first-occurrence argmin
    }
    g_SI[e] = make_int2(sm, im);
    atomicAdd(&g_deg[sm], 0.125f);
    atomicAdd(&g_deg[im], 0.125f);
}

// ----- kA: dinv; scale M1 in place by dinv; intra-block exclusive scan -------
__global__ void kA_scan1(int V) {
    __shared__ int s[1024];
    int t = threadIdx.x;
    int v = blockIdx.x * 1024 + t;
    int c = 0;
    if (v < V) {
        float deg = g_deg[v];
        float dinv = rsqrtf(deg);
        g_deg[v] = dinv;
        c = (int)lrintf((deg - 1.0f) * 8.0f);   // exact: 0.125-sums are exact fp32
        float4 m0 = g_M1[(size_t)v * 2], m1 = g_M1[(size_t)v * 2 + 1];
        g_M1[(size_t)v * 2]     = make_float4(dinv*m0.x, dinv*m0.y, dinv*m0.z, dinv*m0.w);
        g_M1[(size_t)v * 2 + 1] = make_float4(dinv*m1.x, dinv*m1.y, dinv*m1.z, dinv*m1.w);
    }
    s[t] = c;
    __syncthreads();
    for (int off = 1; off < 1024; off <<= 1) {
        int add = (t >= off) ? s[t - off] : 0;
        __syncthreads();
        s[t] += add;
        __syncthreads();
    }
    if (v < V) g_row[v] = s[t] - c;             // intra-block exclusive
    if (t == 1023) g_bsum[blockIdx.x] = s[1023];
}

// ----- kC: scan block sums locally; finalize row starts; init cursors --------
__global__ void kC_finish(int V, int nb, int total) {
    __shared__ int s[1024];
    int t = threadIdx.x;
    s[t] = (t < nb) ? g_bsum[t] : 0;
    __syncthreads();
    for (int off = 1; off < 1024; off <<= 1) {
        int add = (t >= off) ? s[t - off] : 0;
        __syncthreads();
        s[t] += add;
        __syncthreads();
    }
    int b = blockIdx.x;
    int boff = (b == 0) ? 0 : s[b - 1];
    int v = b * 1024 + t;
    if (v < V) {
        int r = g_row[v] + boff;
        g_row[v] = r;
        g_head[v] = r;
    }
    if (b == 0 && t == 0) g_row[V] = total;
}

// ---------------- kF: CSR fill (2M cheap scalar atomics) ---------------------
__global__ void __launch_bounds__(256) kF_fill(int ne) {
    int e = blockIdx.x * blockDim.x + threadIdx.x;
    if (e >= ne) return;
    int2 si = __ldg(&g_SI[e]);
    int p1 = atomicAdd(&g_head[si.x], 1);
    g_csr[p1] = si.y;
    int p2 = atomicAdd(&g_head[si.y], 1);
    g_csr[p2] = si.x;
}

// ------- g1: gather on scaled M1 + relu(+b1) + @W2 -> scaled M2 --------------
__global__ void __launch_bounds__(256) g1_layer(
        const float* __restrict__ b1, const float* __restrict__ W2, int V) {
    __shared__ float sW[64];
    __shared__ float sb[8];
    int t = threadIdx.x;
    if (t < 64) sW[t] = W2[t];
    if (t < 8)  sb[t] = b1[t];
    __syncthreads();
    int v = blockIdx.x * blockDim.x + t;
    if (v >= V) return;
    float dinv = g_deg[v];
    float4 m0 = g_M1[(size_t)v * 2], m1 = g_M1[(size_t)v * 2 + 1];
    float self[8] = {m0.x, m0.y, m0.z, m0.w, m1.x, m1.y, m1.z, m1.w};
    float acc[8] = {0.f, 0.f, 0.f, 0.f, 0.f, 0.f, 0.f, 0.f};
    int start = g_row[v], end = g_row[v + 1];
#pragma unroll 4
    for (int j = start; j < end; j++) {
        int u = __ldg(&g_csr[j]);
        float4 u0 = __ldg(&g_M1[(size_t)u * 2]);
        float4 u1 = __ldg(&g_M1[(size_t)u * 2 + 1]);
        acc[0] += u0.x; acc[1] += u0.y; acc[2] += u0.z; acc[3] += u0.w;
        acc[4] += u1.x; acc[5] += u1.y; acc[6] += u1.z; acc[7] += u1.w;
    }
    float h[8];
#pragma unroll
    for (int k = 0; k < 8; k++)
        h[k] = fmaxf(dinv * fmaf(0.125f, acc[k], self[k]) + sb[k], 0.f);
    float m[8];
#pragma unroll
    for (int k = 0; k < 8; k++) m[k] = 0.f;
#pragma unroll
    for (int d = 0; d < 8; d++)
#pragma unroll
        for (int k = 0; k < 8; k++)
            m[k] = fmaf(h[d], sW[d * 8 + k], m[k]);
    g_M2[(size_t)v * 2]     = make_float4(dinv*m[0], dinv*m[1], dinv*m[2], dinv*m[3]);
    g_M2[(size_t)v * 2 + 1] = make_float4(dinv*m[4], dinv*m[5], dinv*m[6], dinv*m[7]);
}

// ------- g2: gather on scaled M2 + relu(+b2) + @W3 -> scaled M3 (fp16) -------
__global__ void __launch_bounds__(256) g2_layer(
        const float* __restrict__ b2, const float* __restrict__ W3, int V) {
    __shared__ float sW[128];   // [8,16]
    __shared__ float sb[8];
    int t = threadIdx.x;
    if (t < 128) sW[t] = W3[t];
    if (t < 8)   sb[t] = b2[t];
    __syncthreads();
    int v = blockIdx.x * blockDim.x + t;
    if (v >= V) return;
    float dinv = g_deg[v];
    float4 m0 = g_M2[(size_t)v * 2], m1 = g_M2[(size_t)v * 2 + 1];
    float self[8] = {m0.x, m0.y, m0.z, m0.w, m1.x, m1.y, m1.z, m1.w};
    float acc[8] = {0.f, 0.f, 0.f, 0.f, 0.f, 0.f, 0.f, 0.f};
    int start = g_row[v], end = g_row[v + 1];
#pragma unroll 4
    for (int j = start; j < end; j++) {
        int u = __ldg(&g_csr[j]);
        float4 u0 = __ldg(&g_M2[(size_t)u * 2]);
        float4 u1 = __ldg(&g_M2[(size_t)u * 2 + 1]);
        acc[0] += u0.x; acc[1] += u0.y; acc[2] += u0.z; acc[3] += u0.w;
        acc[4] += u1.x; acc[5] += u1.y; acc[6] += u1.z; acc[7] += u1.w;
    }
    float h[8];
#pragma unroll
    for (int k = 0; k < 8; k++)
        h[k] = fmaxf(dinv * fmaf(0.125f, acc[k], self[k]) + sb[k], 0.f);
    float m[16];
#pragma unroll
    for (int k = 0; k < 16; k++) m[k] = 0.f;
#pragma unroll
    for (int d = 0; d < 8; d++)
#pragma unroll
        for (int k = 0; k < 16; k++)
            m[k] = fmaf(h[d], sW[d * 16 + k], m[k]);
    // pack dinv*m into 16 halves (two uint4 = 32B)
    uint4 p0, p1;
    {
        __half2 hh;
        hh = __floats2half2_rn(dinv*m[0],  dinv*m[1]);  p0.x = *(unsigned*)&hh;
        hh = __floats2half2_rn(dinv*m[2],  dinv*m[3]);  p0.y = *(unsigned*)&hh;
        hh = __floats2half2_rn(dinv*m[4],  dinv*m[5]);  p0.z = *(unsigned*)&hh;
        hh = __floats2half2_rn(dinv*m[6],  dinv*m[7]);  p0.w = *(unsigned*)&hh;
        hh = __floats2half2_rn(dinv*m[8],  dinv*m[9]);  p1.x = *(unsigned*)&hh;
        hh = __floats2half2_rn(dinv*m[10], dinv*m[11]); p1.y = *(unsigned*)&hh;
        hh = __floats2half2_rn(dinv*m[12], dinv*m[13]); p1.z = *(unsigned*)&hh;
        hh = __floats2half2_rn(dinv*m[14], dinv*m[15]); p1.w = *(unsigned*)&hh;
    }
    g_M3h[(size_t)v * 2]     = p0;
    g_M3h[(size_t)v * 2 + 1] = p1;
}

__device__ __forceinline__ void acc_half8(float* acc, uint4 p) {
    float2 f;
    f = __half22float2(*(__half2*)&p.x); acc[0] += f.x; acc[1] += f.y;
    f = __half22float2(*(__half2*)&p.y); acc[2] += f.x; acc[3] += f.y;
    f = __half22float2(*(__half2*)&p.z); acc[4] += f.x; acc[5] += f.y;
    f = __half22float2(*(__half2*)&p.w); acc[6] += f.x; acc[7] += f.y;
}

// ------- g3: gather on fp16 M3 (16) + relu(+b3) + fc + sigmoid -> out --------
__global__ void __launch_bounds__(256) g3_layer(
        const float* __restrict__ b3, const float* __restrict__ fcw,
        const float* __restrict__ fcb, float* __restrict__ out, int V) {
    __shared__ float sb[16];
    __shared__ float sw[16];
    __shared__ float sfb;
    int t = threadIdx.x;
    if (t < 16) { sb[t] = b3[t]; sw[t] = fcw[t]; }
    if (t == 0) sfb = fcb[0];
    __syncthreads();
    int v = blockIdx.x * blockDim.x + t;
    if (v >= V) return;
    float dinv = g_deg[v];
    float self[16] = {0}, acc[16];
#pragma unroll
    for (int k = 0; k < 16; k++) acc[k] = 0.f;
    acc_half8(self,     __ldg(&g_M3h[(size_t)v * 2]));
    acc_half8(self + 8, __ldg(&g_M3h[(size_t)v * 2 + 1]));
    int start = g_row[v], end = g_row[v + 1];
#pragma unroll 4
    for (int j = start; j < end; j++) {
        int u = __ldg(&g_csr[j]);
        acc_half8(acc,     __ldg(&g_M3h[(size_t)u * 2]));
        acc_half8(acc + 8, __ldg(&g_M3h[(size_t)u * 2 + 1]));
    }
    float logit = sfb;
#pragma unroll
    for (int k = 0; k < 16; k++)
        logit = fmaf(fmaxf(dinv * fmaf(0.125f, acc[k], self[k]) + sb[k], 0.f),
                     sw[k], logit);
    out[v] = 1.0f / (1.0f + expf(-logit));
}

// ---------------- launch ------------------------------------------------------
extern "C" void kernel_launch(void* const* d_in, const int* in_sizes, int n_in,
                              void* d_out, int out_size) {
    const float*     X   = (const float*)d_in[0];
    const long long* E   = (const long long*)d_in[1];
    const float*     rv  = (const float*)d_in[2];
    const float*     W1  = (const float*)d_in[3];
    const float*     b1  = (const float*)d_in[4];
    const float*     W2  = (const float*)d_in[5];
    const float*     b2  = (const float*)d_in[6];
    const float*     W3  = (const float*)d_in[7];
    const float*     b3  = (const float*)d_in[8];
    const float*     fcw = (const float*)d_in[9];
    const float*     fcb = (const float*)d_in[10];
    float*           out = (float*)d_out;

    int V  = in_sizes[0] / 128;
    int ne = in_sizes[1] / 8;
    int nb = (V + 1023) / 1024;

    dim3 blk(256);
    int gb_node = (V + 255) / 256;
    int gb_edge = (ne + 255) / 256;
    int gb_k1   = (V + 31) / 32;

    k1_proj_xw1<<<gb_k1, blk>>>(X, rv, W1, V);
    k2_edges<<<gb_edge, blk>>>(E, ne, V);
    kA_scan1<<<nb, 1024>>>(V);
    kC_finish<<<nb, 1024>>>(V, nb, 2 * ne);
    kF_fill<<<gb_edge, blk>>>(ne);
    g1_layer<<<gb_node, blk>>>(b1, W2, V);      // ncu -s 5 lands here now
    g2_layer<<<gb_node, blk>>>(b2, W3, V);
    g3_layer<<<gb_node, blk>>>(b3, fcw, fcb, out, V);
}

// round 7
// speedup vs baseline: 2.7321x; 1.0630x over previous
#include <cuda_runtime.h>
#include <cuda_fp16.h>

// HyperGCN: CSR-gather, fp16 feature tables for all gather layers.
// V=500000, D=128, NE=1e6, K=8, H1=8, C=16.

#define VN    500000
#define NEDGE 1000000

// ---------------- scratch (device globals; no allocation allowed) ------------
__device__ float  g_proj[VN];          // X @ rv
__device__ float  g_deg[VN];           // degree, then overwritten with rsqrt(degree)
__device__ int    g_row[VN + 1];       // CSR row starts (prefix, +1 sentinel)
__device__ int    g_head[VN];          // fill cursors
__device__ int2   g_SI[NEDGE];         // (Se, Ie) per edge
__device__ int    g_csr[2 * NEDGE];    // source node per directed edge
__device__ int    g_bsum[1024];
__device__ int    g_boff[1024];
__device__ float4 g_M1[VN * 2];        // X@W1 fp32 (written by k1, consumed by kA)
__device__ uint4  g_M1h[VN];           // dinv*(X@W1)  fp16, 8 halves = 16B/row
__device__ uint4  g_M2h[VN];           // dinv*(h1@W2) fp16, 16B/row
__device__ uint4  g_M3h[VN * 2];       // dinv*(h2@W3) fp16, 16 halves = 32B/row

// ---------------- helpers ----------------------------------------------------
__device__ __forceinline__ uint4 pack8_half(const float* m, float s) {
    uint4 p;
    __half2 hh;
    hh = __floats2half2_rn(s*m[0], s*m[1]); p.x = *(unsigned*)&hh;
    hh = __floats2half2_rn(s*m[2], s*m[3]); p.y = *(unsigned*)&hh;
    hh = __floats2half2_rn(s*m[4], s*m[5]); p.z = *(unsigned*)&hh;
    hh = __floats2half2_rn(s*m[6], s*m[7]); p.w = *(unsigned*)&hh;
    return p;
}
__device__ __forceinline__ void acc_half8(float* acc, uint4 p) {
    float2 f;
    f = __half22float2(*(__half2*)&p.x); acc[0] += f.x; acc[1] += f.y;
    f = __half22float2(*(__half2*)&p.y); acc[2] += f.x; acc[3] += f.y;
    f = __half22float2(*(__half2*)&p.z); acc[4] += f.x; acc[5] += f.y;
    f = __half22float2(*(__half2*)&p.w); acc[6] += f.x; acc[7] += f.y;
}

// ---------------- K1: fused proj = X@rv and M1 = X@W1, deg init --------------
__global__ void __launch_bounds__(256) k1_proj_xw1(
        const float* __restrict__ X,
        const float* __restrict__ rv,
        const float* __restrict__ W1, int V) {
    __shared__ float s_rv[128];
    __shared__ float s_W1t[8 * 128];   // [h][d]
    int t = threadIdx.x;
    if (t < 128) s_rv[t] = rv[t];
    for (int i = t; i < 1024; i += blockDim.x) {
        int d = i >> 3, h = i & 7;
        s_W1t[h * 128 + d] = W1[i];    // W1 is [d][h] row-major
    }
    __syncthreads();

    int lane = t & 31;
    int l8   = lane & 7;
    int grp  = lane >> 3;
    int warp = t >> 5;
    int row  = blockIdx.x * 32 + warp * 4 + grp;
    bool valid = row < V;
    int r = valid ? row : 0;

    const float4* Xr = (const float4*)X + (size_t)r * 32;
    float accP = 0.f;
    float accW[8];
#pragma unroll
    for (int h = 0; h < 8; h++) accW[h] = 0.f;

#pragma unroll
    for (int j = 0; j < 4; j++) {
        float4 x = Xr[l8 + j * 8];
        int d0 = j * 32 + l8 * 4;
        float4 rv4 = *(const float4*)&s_rv[d0];
        accP = fmaf(x.x, rv4.x, accP);
        accP = fmaf(x.y, rv4.y, accP);
        accP = fmaf(x.z, rv4.z, accP);
        accP = fmaf(x.w, rv4.w, accP);
#pragma unroll
        for (int h = 0; h < 8; h++) {
            float4 w = *(const float4*)&s_W1t[h * 128 + d0];
            accW[h] = fmaf(x.x, w.x, accW[h]);
            accW[h] = fmaf(x.y, w.y, accW[h]);
            accW[h] = fmaf(x.z, w.z, accW[h]);
            accW[h] = fmaf(x.w, w.w, accW[h]);
        }
    }
#pragma unroll
    for (int off = 4; off; off >>= 1) {
        accP += __shfl_xor_sync(0xffffffffu, accP, off);
#pragma unroll
        for (int h = 0; h < 8; h++)
            accW[h] += __shfl_xor_sync(0xffffffffu, accW[h], off);
    }
    if (valid && l8 == 0) {
        g_proj[row] = accP;
        g_M1[(size_t)row * 2 + 0] = make_float4(accW[0], accW[1], accW[2], accW[3]);
        g_M1[(size_t)row * 2 + 1] = make_float4(accW[4], accW[5], accW[6], accW[7]);
        g_deg[row] = 1.0f;                      // identity contribution
    }
}

// ------- K2: inline dtype detect + per-edge argmax/argmin + degrees ----------
__global__ void __launch_bounds__(256) k2_edges(const long long* __restrict__ E, int ne, int V) {
    __shared__ int s_is64;
    if (threadIdx.x == 0) s_is64 = 1;
    __syncthreads();
    if (threadIdx.x < 64) {
        long long v = E[threadIdx.x];
        if (v < 0 || v >= (long long)V) atomicAnd(&s_is64, 0);
    }
    __syncthreads();
    int is64 = s_is64;

    int e = blockIdx.x * blockDim.x + threadIdx.x;
    if (e >= ne) return;
    int idx[8];
    if (is64) {
        const longlong2* Er = (const longlong2*)(E + (size_t)e * 8);
#pragma unroll
        for (int j = 0; j < 4; j++) {
            longlong2 v = Er[j];
            idx[2 * j] = (int)v.x; idx[2 * j + 1] = (int)v.y;
        }
    } else {
        const int4* Ei = (const int4*)((const int*)E + (size_t)e * 8);
        int4 a = Ei[0], b = Ei[1];
        idx[0] = a.x; idx[1] = a.y; idx[2] = a.z; idx[3] = a.w;
        idx[4] = b.x; idx[5] = b.y; idx[6] = b.z; idx[7] = b.w;
    }
    float pm = __ldg(&g_proj[idx[0]]), pn = pm;
    int sm = idx[0], im = idx[0];
#pragma unroll
    for (int j = 1; j < 8; j++) {
        float p = __ldg(&g_proj[idx[j]]);
        if (p > pm) { pm = p; sm = idx[j]; }    // strict: first-occurrence argmax
        if (p < pn) { pn = p; im = idx[j]; }    // strict: first-occurrence argmin
    }
    g_SI[e] = make_int2(sm, im);
    atomicAdd(&g_deg[sm], 0.125f);
    atomicAdd(&g_deg[im], 0.125f);
}

// ----- kA: dinv; M1 -> fp16 scaled; warp-shuffle block exclusive scan --------
__global__ void kA_scan1(int V) {
    __shared__ int wsum[32];
    int t = threadIdx.x;
    int v = blockIdx.x * 1024 + t;
    int c = 0;
    if (v < V) {
        float deg = g_deg[v];
        float dinv = rsqrtf(deg);
        g_deg[v] = dinv;
        c = (int)lrintf((deg - 1.0f) * 8.0f);   // exact: 0.125-sums are exact fp32
        float4 m0 = g_M1[(size_t)v * 2], m1 = g_M1[(size_t)v * 2 + 1];
        float m[8] = {m0.x, m0.y, m0.z, m0.w, m1.x, m1.y, m1.z, m1.w};
        g_M1h[v] = pack8_half(m, dinv);
    }
    int lane = t & 31, warp = t >> 5;
    int inc = c;
#pragma unroll
    for (int off = 1; off < 32; off <<= 1) {
        int n = __shfl_up_sync(0xffffffffu, inc, off);
        if (lane >= off) inc += n;
    }
    if (lane == 31) wsum[warp] = inc;
    __syncthreads();
    if (warp == 0) {
        int ws = wsum[lane];
#pragma unroll
        for (int off = 1; off < 32; off <<= 1) {
            int n = __shfl_up_sync(0xffffffffu, ws, off);
            if (lane >= off) ws += n;
        }
        wsum[lane] = ws;                        // inclusive warp sums
    }
    __syncthreads();
    int base = (warp == 0) ? 0 : wsum[warp - 1];
    if (v < V) g_row[v] = base + inc - c;       // block-exclusive
    if (t == 1023) g_bsum[blockIdx.x] = base + inc;
}

// ----- kB: scan block sums (1 block, warp-shuffle) ---------------------------
__global__ void kB_scan2(int nb) {
    __shared__ int wsum[32];
    int t = threadIdx.x;                        // 1024 threads
    int lane = t & 31, warp = t >> 5;
    int c = (t < nb) ? g_bsum[t] : 0;
    int inc = c;
#pragma unroll
    for (int off = 1; off < 32; off <<= 1) {
        int n = __shfl_up_sync(0xffffffffu, inc, off);
        if (lane >= off) inc += n;
    }
    if (lane == 31) wsum[warp] = inc;
    __syncthreads();
    if (warp == 0) {
        int ws = wsum[lane];
#pragma unroll
        for (int off = 1; off < 32; off <<= 1) {
            int n = __shfl_up_sync(0xffffffffu, ws, off);
            if (lane >= off) ws += n;
        }
        wsum[lane] = ws;
    }
    __syncthreads();
    int base = (warp == 0) ? 0 : wsum[warp - 1];
    g_boff[t] = base + inc - c;                 // exclusive
}

// ----- kC: finalize row starts (pure streaming), init cursors ----------------
__global__ void __launch_bounds__(256) kC_finish(int V, int total) {
    int v = blockIdx.x * blockDim.x + threadIdx.x;
    if (v < V) {
        int r = g_row[v] + g_boff[v >> 10];
        g_row[v] = r;
        g_head[v] = r;
    }
    if (v == 0) g_row[V] = total;
}

// ---------------- kF: CSR fill (2M cheap scalar atomics) ---------------------
__global__ void __launch_bounds__(256) kF_fill(int ne) {
    int e = blockIdx.x * blockDim.x + threadIdx.x;
    if (e >= ne) return;
    int2 si = __ldg(&g_SI[e]);
    int p1 = atomicAdd(&g_head[si.x], 1);
    g_csr[p1] = si.y;
    int p2 = atomicAdd(&g_head[si.y], 1);
    g_csr[p2] = si.x;
}

// ------- g1: gather on fp16 M1 + relu(+b1) + @W2 -> fp16 M2 ------------------
__global__ void __launch_bounds__(256) g1_layer(
        const float* __restrict__ b1, const float* __restrict__ W2, int V) {
    __shared__ float sW[64];
    __shared__ float sb[8];
    int t = threadIdx.x;
    if (t < 64) sW[t] = W2[t];
    if (t < 8)  sb[t] = b1[t];
    __syncthreads();
    int v = blockIdx.x * blockDim.x + t;
    if (v >= V) return;
    float dinv = g_deg[v];
    float self[8] = {0,0,0,0,0,0,0,0};
    acc_half8(self, __ldg(&g_M1h[v]));
    float acc[8] = {0,0,0,0,0,0,0,0};
    int start = g_row[v], end = g_row[v + 1];
#pragma unroll 4
    for (int j = start; j < end; j++) {
        int u = __ldg(&g_csr[j]);
        acc_half8(acc, __ldg(&g_M1h[u]));
    }
    float h[8];
#pragma unroll
    for (int k = 0; k < 8; k++)
        h[k] = fmaxf(dinv * fmaf(0.125f, acc[k], self[k]) + sb[k], 0.f);
    float m[8];
#pragma unroll
    for (int k = 0; k < 8; k++) m[k] = 0.f;
#pragma unroll
    for (int d = 0; d < 8; d++)
#pragma unroll
        for (int k = 0; k < 8; k++)
            m[k] = fmaf(h[d], sW[d * 8 + k], m[k]);
    g_M2h[v] = pack8_half(m, dinv);
}

// ------- g2: gather on fp16 M2 + relu(+b2) + @W3 -> fp16 M3 (16) -------------
__global__ void __launch_bounds__(256) g2_layer(
        const float* __restrict__ b2, const float* __restrict__ W3, int V) {
    __shared__ float sW[128];   // [8,16]
    __shared__ float sb[8];
    int t = threadIdx.x;
    if (t < 128) sW[t] = W3[t];
    if (t < 8)   sb[t] = b2[t];
    __syncthreads();
    int v = blockIdx.x * blockDim.x + t;
    if (v >= V) return;
    float dinv = g_deg[v];
    float self[8] = {0,0,0,0,0,0,0,0};
    acc_half8(self, __ldg(&g_M2h[v]));
    float acc[8] = {0,0,0,0,0,0,0,0};
    int start = g_row[v], end = g_row[v + 1];
#pragma unroll 4
    for (int j = start; j < end; j++) {
        int u = __ldg(&g_csr[j]);
        acc_half8(acc, __ldg(&g_M2h[u]));
    }
    float h[8];
#pragma unroll
    for (int k = 0; k < 8; k++)
        h[k] = fmaxf(dinv * fmaf(0.125f, acc[k], self[k]) + sb[k], 0.f);
    float m[16];
#pragma unroll
    for (int k = 0; k < 16; k++) m[k] = 0.f;
#pragma unroll
    for (int d = 0; d < 8; d++)
#pragma unroll
        for (int k = 0; k < 16; k++)
            m[k] = fmaf(h[d], sW[d * 16 + k], m[k]);
    g_M3h[(size_t)v * 2]     = pack8_half(m,     dinv);
    g_M3h[(size_t)v * 2 + 1] = pack8_half(m + 8, dinv);
}

// ------- g3: gather on fp16 M3 (16) + relu(+b3) + fc + sigmoid -> out --------
__global__ void __launch_bounds__(256) g3_layer(
        const float* __restrict__ b3, const float* __restrict__ fcw,
        const float* __restrict__ fcb, float* __restrict__ out, int V) {
    __shared__ float sb[16];
    __shared__ float sw[16];
    __shared__ float sfb;
    int t = threadIdx.x;
    if (t < 16) { sb[t] = b3[t]; sw[t] = fcw[t]; }
    if (t == 0) sfb = fcb[0];
    __syncthreads();
    int v = blockIdx.x * blockDim.x + t;
    if (v >= V) return;
    float dinv = g_deg[v];
    float self[16] = {0}, acc[16];
#pragma unroll
    for (int k = 0; k < 16; k++) acc[k] = 0.f;
    acc_half8(self,     __ldg(&g_M3h[(size_t)v * 2]));
    acc_half8(self + 8, __ldg(&g_M3h[(size_t)v * 2 + 1]));
    int start = g_row[v], end = g_row[v + 1];
#pragma unroll 4
    for (int j = start; j < end; j++) {
        int u = __ldg(&g_csr[j]);
        acc_half8(acc,     __ldg(&g_M3h[(size_t)u * 2]));
        acc_half8(acc + 8, __ldg(&g_M3h[(size_t)u * 2 + 1]));
    }
    float logit = sfb;
#pragma unroll
    for (int k = 0; k < 16; k++)
        logit = fmaf(fmaxf(dinv * fmaf(0.125f, acc[k], self[k]) + sb[k], 0.f),
                     sw[k], logit);
    out[v] = 1.0f / (1.0f + expf(-logit));
}

// ---------------- launch ------------------------------------------------------
extern "C" void kernel_launch(void* const* d_in, const int* in_sizes, int n_in,
                              void* d_out, int out_size) {
    const float*     X   = (const float*)d_in[0];
    const long long* E   = (const long long*)d_in[1];
    const float*     rv  = (const float*)d_in[2];
    const float*     W1  = (const float*)d_in[3];
    const float*     b1  = (const float*)d_in[4];
    const float*     W2  = (const float*)d_in[5];
    const float*     b2  = (const float*)d_in[6];
    const float*     W3  = (const float*)d_in[7];
    const float*     b3  = (const float*)d_in[8];
    const float*     fcw = (const float*)d_in[9];
    const float*     fcb = (const float*)d_in[10];
    float*           out = (float*)d_out;

    int V  = in_sizes[0] / 128;
    int ne = in_sizes[1] / 8;
    int nb = (V + 1023) / 1024;

    dim3 blk(256);
    int gb_node = (V + 255) / 256;
    int gb_edge = (ne + 255) / 256;
    int gb_k1   = (V + 31) / 32;

    k1_proj_xw1<<<gb_k1, blk>>>(X, rv, W1, V);
    k2_edges<<<gb_edge, blk>>>(E, ne, V);
    kA_scan1<<<nb, 1024>>>(V);
    kB_scan2<<<1, 1024>>>(nb);
    kC_finish<<<gb_node, blk>>>(V, 2 * ne);
    kF_fill<<<gb_edge, blk>>>(ne);
    g1_layer<<<gb_node, blk>>>(b1, W2, V);
    g2_layer<<<gb_node, blk>>>(b2, W3, V);
    g3_layer<<<gb_node, blk>>>(b3, fcw, fcb, out, V);
}